// round 7
// baseline (speedup 1.0000x reference)
#include <cuda_runtime.h>
#include <cuda_bf16.h>
#include <cstdint>

// VQ-VAE eval forward, GB300 (sm_103a die, harness targets sm_103 base ISA).
// Round 7: shortlist GEMM switched bf16 HMMA.16816 -> int8 IMMA.16832.
// Rationale: round 6 measured 77 TF/s ~= one mma.sync per ~64 SMSP-cycles
// (fallback tensor path is per-INSTRUCTION limited). k32 int8 halves the
// instruction count for the same GEMM. Integer dot is exact; only operand
// quantization errs (sigma_u ~ 1e-2). MARGIN = 20 sigma; overflow -> exact
// full scan makes candidate containment structural. Exact fp32 refine
// (round-3-proven reference ranking) unchanged.

#define KC      2048
#define DD      256
#define BETA_F  0.25f
#define MAXROWS 32768
#define MARGIN  0.2f

#define TILE_M  128
#define TILE_N  128
#define NTILES  (KC / TILE_N)     // 16

// smem layout (bytes). A: int8 128x256, row = 136 b16 units (272B, 68 words
// == 4 mod 32 banks -> conflict-free ldmatrix). B: int8 128x128 per buffer,
// row = 72 b16 units (144B, 36 words == 4 mod 32).
#define APITCH  136               // b16 units per A row
#define BPITCH  72                // b16 units per B row
#define OFF_A   0
#define ABYTES  (TILE_M * APITCH * 2)              // 34816
#define OFF_B   ABYTES
#define BBYTES  (TILE_N * BPITCH * 2)              // 18432
#define OFF_US  (OFF_B + 2 * BBYTES)               // 71680
#define USBYTES (128 * 128 * 4)                    // 65536
#define OFF_E2  (OFF_US + USBYTES)                 // 137216
#define OFF_SW  (OFF_E2 + 512)
#define OFF_SZ  (OFF_SW + 512)
#define SMEM_TOTAL (OFF_SZ + 512)                  // 138752

// ---- static device scratch ----
__device__ float   g_e2[KC];
__device__ float   g_sw[KC];                 // per-code int8 scale
__device__ int8_t  g_Wq[KC * DD];            // quantized codebook
__device__ int     g_cand[MAXROWS * 8];
__device__ int     g_ncand[MAXROWS];
__device__ int     g_counts[KC];
__device__ float   g_partials[MAXROWS];

// ============================================================================
// helpers
// ============================================================================
__device__ __forceinline__ uint32_t smem_u32(const void* p) {
    uint32_t a;
    asm("{ .reg .u64 t; cvta.to.shared.u64 t, %1; cvt.u32.u64 %0, t; }" : "=r"(a) : "l"(p));
    return a;
}

__device__ __forceinline__ void ldsm_x4(uint32_t& r0, uint32_t& r1, uint32_t& r2,
                                        uint32_t& r3, uint32_t addr) {
    asm volatile("ldmatrix.sync.aligned.m8n8.x4.shared.b16 {%0,%1,%2,%3}, [%4];"
                 : "=r"(r0), "=r"(r1), "=r"(r2), "=r"(r3) : "r"(addr));
}

// m16n8k32 int8 MMA; fragment layout is b16-pairing-identical to m16n8k16.bf16
__device__ __forceinline__ void mma16832s8(int* c, const uint32_t* a, const uint32_t* b) {
    asm volatile("mma.sync.aligned.m16n8k32.row.col.s32.s8.s8.s32 "
                 "{%0,%1,%2,%3}, {%4,%5,%6,%7}, {%8,%9}, {%0,%1,%2,%3};"
                 : "+r"(c[0]), "+r"(c[1]), "+r"(c[2]), "+r"(c[3])
                 : "r"(a[0]), "r"(a[1]), "r"(a[2]), "r"(a[3]), "r"(b[0]), "r"(b[1]));
}

// bank swizzle for the score buffer (bijective in low 5 column bits per row)
__device__ __forceinline__ int fswz(int r) {
    return (r & 1) | (((r >> 3) & 3) << 1) | (((r >> 1) & 3) << 3);
}

__device__ __forceinline__ int q8(float v, float inv) {
    return __float2int_rn(v * inv);     // |v*inv| <= 127 by construction
}

// ============================================================================
// prep: e2[k] (fp32 tree, exact-refine input), per-code scale, int8 quantize,
// zero histogram. grid = KC, block = 256.
// ============================================================================
__global__ void vq_prep_kernel(const float* __restrict__ W) {
    int row = blockIdx.x, tid = threadIdx.x;
    float w = W[(size_t)row * DD + tid];
    __shared__ float red[256];
    __shared__ float rmx[256];
    red[tid] = w * w;
    rmx[tid] = fabsf(w);
    __syncthreads();
    for (int s = 128; s > 0; s >>= 1) {
        if (tid < s) {
            red[tid] += red[tid + s];
            rmx[tid] = fmaxf(rmx[tid], rmx[tid + s]);
        }
        __syncthreads();
    }
    if (tid == 0) {
        g_e2[row] = red[0];
        float mx = fmaxf(rmx[0], 1e-20f);
        g_sw[row] = mx / 127.0f;
        rmx[0] = 127.0f / mx;
        g_counts[row] = 0;
    }
    __syncthreads();
    g_Wq[(size_t)row * DD + tid] = (int8_t)q8(w, rmx[0]);
}

// ============================================================================
// phase 1: int8 IMMA approx-score GEMM + per-row top-8 candidate band.
// 256 threads (8 warps: 4x2 over 128x128), grid = n_rows/128.
// ============================================================================
__global__ __launch_bounds__(256)
void vq_imma_kernel(const float* __restrict__ Z) {
    extern __shared__ char smem[];
    const uint32_t sb = smem_u32(smem);
    const int tid = threadIdx.x;
    const int lane = tid & 31, wid = tid >> 5;
    const int wm = wid & 3, wn = wid >> 2;
    const int grp = lane >> 3, lr = lane & 7;
    const int rowBase = blockIdx.x * TILE_M;
    float* Us  = (float*)(smem + OFF_US);
    float* e2s = (float*)(smem + OFF_E2);
    float* sws = (float*)(smem + OFF_SW);
    float* szs = (float*)(smem + OFF_SZ);

    // ---- ldmatrix lane addresses (b16 units; identical mapping to round 6) ----
    uint32_t aAddr[2];
#pragma unroll
    for (int f = 0; f < 2; ++f) {
        int r = wm * 32 + f * 16 + (grp & 1) * 8 + lr;
        int kof = (grp >> 1) * 8;
        aAddr[f] = sb + OFF_A + (uint32_t)(r * APITCH + kof) * 2u;
    }
    uint32_t bAddr[4];
#pragma unroll
    for (int p = 0; p < 4; ++p) {
        int n = wn * 64 + p * 16 + (grp >> 1) * 8 + lr;
        int kof = (grp & 1) * 8;
        bAddr[p] = sb + OFF_B + (uint32_t)(n * BPITCH + kof) * 2u;
    }

    // ---- A tile: per-row max -> scale -> int8 quantize into smem ----
    {
        int r = tid >> 1, hf = tid & 1;
        const float4* src = (const float4*)(Z + (size_t)(rowBase + r) * DD + hf * 128);
        float mx = 0.0f;
#pragma unroll 8
        for (int j = 0; j < 32; ++j) {
            float4 v = src[j];
            mx = fmaxf(mx, fmaxf(fmaxf(fabsf(v.x), fabsf(v.y)),
                                 fmaxf(fabsf(v.z), fabsf(v.w))));
        }
        mx = fmaxf(mx, __shfl_xor_sync(0xffffffffu, mx, 1));   // partner = other half
        mx = fmaxf(mx, 1e-20f);
        float inv = 127.0f / mx;
        if (hf == 0) szs[r] = mx / 127.0f;
        uint32_t* dst = (uint32_t*)(smem + OFF_A) + r * (APITCH / 2) + hf * 32;
#pragma unroll 8
        for (int j = 0; j < 32; ++j) {
            float4 v = src[j];                                  // L1-hot reload
            uint32_t p = (uint32_t)(q8(v.x, inv) & 255)
                       | ((uint32_t)(q8(v.y, inv) & 255) << 8)
                       | ((uint32_t)(q8(v.z, inv) & 255) << 16)
                       | ((uint32_t)(q8(v.w, inv) & 255) << 24);
            dst[j] = p;
        }
    }

    // ---- top-8 state (ascending u) ----
    float u0 = 3.4e38f, u1 = 3.4e38f, u2 = 3.4e38f, u3 = 3.4e38f,
          u4 = 3.4e38f, u5 = 3.4e38f, u6 = 3.4e38f, u7 = 3.4e38f;
    int   k0 = 0, k1 = 0, k2 = 0, k3 = 0, k4 = 0, k5 = 0, k6 = 0, k7 = 0;
    const int myf = fswz(tid & 127);

    int   acc[2][8][4];
    uint4 rb[4];

    // prefetch B tile 0 (int8: 16KB -> 4 uint4 per thread)
    {
        int n = tid >> 1, hf = tid & 1;
        const uint4* src = (const uint4*)(g_Wq + (size_t)n * DD + hf * 64);
#pragma unroll
        for (int j = 0; j < 4; ++j) rb[j] = src[j];
    }

    for (int t = 0; t < 2 * NTILES; ++t) {
        const int nt = t >> 1, kt = t & 1, buf = t & 1;
        const uint32_t bufOff = (uint32_t)buf * BBYTES;

        __syncthreads();                       // prior readers of Bs[buf] done
        {   // store prefetched regs -> Bs[buf]
            int n = tid >> 1, hf = tid & 1;
            uint4* dst = (uint4*)(smem + OFF_B + bufOff + (uint32_t)n * BPITCH * 2u
                                  + (uint32_t)hf * 64u);
#pragma unroll
            for (int j = 0; j < 4; ++j) dst[j] = rb[j];
        }
        if (kt == 0 && tid < 128) {
            e2s[tid] = g_e2[nt * 128 + tid];
            sws[tid] = g_sw[nt * 128 + tid];
        }
        if (t + 1 < 2 * NTILES) {              // prefetch next tile
            int tn = t + 1;
            int n = tid >> 1, hf = tid & 1;
            const uint4* src = (const uint4*)(g_Wq
                + (size_t)((tn >> 1) * 128 + n) * DD + (tn & 1) * 128 + hf * 64);
#pragma unroll
            for (int j = 0; j < 4; ++j) rb[j] = src[j];
        }
        __syncthreads();                       // Bs[buf] visible

        if (kt == 0) {
#pragma unroll
            for (int mf = 0; mf < 2; ++mf)
#pragma unroll
                for (int nf = 0; nf < 8; ++nf)
#pragma unroll
                    for (int c = 0; c < 4; ++c) acc[mf][nf][c] = 0;
        }

        // 4 k-steps of k32 (128 int8 = 64 b16 per buffer)
#pragma unroll
        for (int ks = 0; ks < 4; ++ks) {
            uint32_t a[2][4], b[8][2];
            ldsm_x4(a[0][0], a[0][1], a[0][2], a[0][3],
                    aAddr[0] + (uint32_t)(kt * 64 + ks * 16) * 2u);
            ldsm_x4(a[1][0], a[1][1], a[1][2], a[1][3],
                    aAddr[1] + (uint32_t)(kt * 64 + ks * 16) * 2u);
#pragma unroll
            for (int p = 0; p < 4; ++p)
                ldsm_x4(b[2 * p][0], b[2 * p][1], b[2 * p + 1][0], b[2 * p + 1][1],
                        bAddr[p] + bufOff + (uint32_t)(ks * 16) * 2u);
#pragma unroll
            for (int mf = 0; mf < 2; ++mf)
#pragma unroll
                for (int nf = 0; nf < 8; ++nf)
                    mma16832s8(acc[mf][nf], a[mf], b[nf]);
        }

        if (kt == 1) {
            // ---- stage u = e2 - 2*sz*sw*dot into swizzled smem ----
#pragma unroll
            for (int mf = 0; mf < 2; ++mf) {
                int r0 = wm * 32 + mf * 16 + (lane >> 2);
                int r1 = r0 + 8;
                float sz0 = szs[r0], sz1 = szs[r1];
#pragma unroll
                for (int nf = 0; nf < 8; ++nf) {
                    int c0 = wn * 64 + nf * 8 + 2 * (lane & 3);
                    float e0 = e2s[c0], e1 = e2s[c0 + 1];
                    float w0 = sws[c0], w1 = sws[c0 + 1];
                    Us[r0 * 128 + ((c0)     ^ fswz(r0))] =
                        fmaf(-2.0f * sz0 * w0, __int2float_rn(acc[mf][nf][0]), e0);
                    Us[r0 * 128 + ((c0 + 1) ^ fswz(r0))] =
                        fmaf(-2.0f * sz0 * w1, __int2float_rn(acc[mf][nf][1]), e1);
                    Us[r1 * 128 + ((c0)     ^ fswz(r1))] =
                        fmaf(-2.0f * sz1 * w0, __int2float_rn(acc[mf][nf][2]), e0);
                    Us[r1 * 128 + ((c0 + 1) ^ fswz(r1))] =
                        fmaf(-2.0f * sz1 * w1, __int2float_rn(acc[mf][nf][3]), e1);
                }
            }
            __syncthreads();
            if (tid < 128) {
                const float* urow = Us + tid * 128;
                int kbase = nt * 128;
#pragma unroll 4
                for (int c = 0; c < 128; ++c) {
                    float u = urow[c ^ myf];
                    if (u < u7) {
                        u7 = u; k7 = kbase + c;
                        if (u7 < u6) { float tu = u6; u6 = u7; u7 = tu; int tk = k6; k6 = k7; k7 = tk; }
                        if (u6 < u5) { float tu = u5; u5 = u6; u6 = tu; int tk = k5; k5 = k6; k6 = tk; }
                        if (u5 < u4) { float tu = u4; u4 = u5; u5 = tu; int tk = k4; k4 = k5; k5 = tk; }
                        if (u4 < u3) { float tu = u3; u3 = u4; u4 = tu; int tk = k3; k3 = k4; k4 = tk; }
                        if (u3 < u2) { float tu = u2; u2 = u3; u3 = tu; int tk = k2; k2 = k3; k3 = tk; }
                        if (u2 < u1) { float tu = u1; u1 = u2; u2 = tu; int tk = k1; k1 = k2; k2 = tk; }
                        if (u1 < u0) { float tu = u0; u0 = u1; u1 = tu; int tk = k0; k0 = k1; k1 = tk; }
                    }
                }
            }
        }
    }

    if (tid < 128) {
        int row = rowBase + tid;
        float thr = u0 + MARGIN;
        int cnt = 1 + (u1 <= thr) + (u2 <= thr) + (u3 <= thr) + (u4 <= thr)
                    + (u5 <= thr) + (u6 <= thr) + (u7 <= thr);
        g_cand[row * 8 + 0] = k0; g_cand[row * 8 + 1] = k1;
        g_cand[row * 8 + 2] = k2; g_cand[row * 8 + 3] = k3;
        g_cand[row * 8 + 4] = k4; g_cand[row * 8 + 5] = k5;
        g_cand[row * 8 + 6] = k6; g_cand[row * 8 + 7] = k7;
        g_ncand[row] = (cnt == 8) ? 9 : cnt;   // 9 = overflow -> exact full scan
    }
}

// ============================================================================
// phase 2: exact fp32 re-rank of candidates (reference ranking pipeline,
// lexicographic (s,k) == first-index ties) fused with gather/MSE/histogram.
// warp per row; grid = n_rows/8, block 256.
// ============================================================================
__global__ __launch_bounds__(256)
void vq_refine_gather_kernel(const float* __restrict__ Z, const float* __restrict__ W,
                             float* __restrict__ out, int n_rows, int write_idx) {
    const int lane = threadIdx.x & 31;
    const int row = blockIdx.x * 8 + (threadIdx.x >> 5);

    float4 z0 = *(const float4*)&Z[(size_t)row * DD + lane * 8];
    float4 z1 = *(const float4*)&Z[(size_t)row * DD + lane * 8 + 4];
    float p = z0.x * z0.x + z0.y * z0.y + z0.z * z0.z + z0.w * z0.w
            + z1.x * z1.x + z1.y * z1.y + z1.z * z1.z + z1.w * z1.w;
#pragma unroll
    for (int off = 16; off > 0; off >>= 1) p += __shfl_xor_sync(0xffffffffu, p, off);
    const float z2 = p;

    int nc = g_ncand[row];
    float sbest = 3.4e38f;
    int kbest = 0;
    int iters = (nc <= 8) ? nc : KC;
    for (int i = 0; i < iters; ++i) {
        int k = (nc <= 8) ? g_cand[row * 8 + i] : i;
        float4 w0 = *(const float4*)&W[(size_t)k * DD + lane * 8];
        float4 w1 = *(const float4*)&W[(size_t)k * DD + lane * 8 + 4];
        float d = z0.x * w0.x + z0.y * w0.y + z0.z * w0.z + z0.w * w0.w
                + z1.x * w1.x + z1.y * w1.y + z1.z * w1.z + z1.w * w1.w;
#pragma unroll
        for (int off = 16; off > 0; off >>= 1) d += __shfl_xor_sync(0xffffffffu, d, off);
        float u = (z2 - 2.0f * d) + g_e2[k];
        float s = sqrtf(fmaxf(u, 0.0f));
        if (s < sbest || (s == sbest && k < kbest)) { sbest = s; kbest = k; }
    }

    // ---- gather + MSE partial + histogram ----
    float4 w0 = *(const float4*)&W[(size_t)kbest * DD + lane * 8];
    float4 w1 = *(const float4*)&W[(size_t)kbest * DD + lane * 8 + 4];
    float d0 = w0.x - z0.x, d1 = w0.y - z0.y, d2 = w0.z - z0.z, d3 = w0.w - z0.w;
    float d4 = w1.x - z1.x, d5 = w1.y - z1.y, d6 = w1.z - z1.z, d7 = w1.w - z1.w;
    *(float4*)&out[(size_t)row * DD + lane * 8] =
        make_float4(z0.x + d0, z0.y + d1, z0.z + d2, z0.w + d3);
    *(float4*)&out[(size_t)row * DD + lane * 8 + 4] =
        make_float4(z1.x + d4, z1.y + d5, z1.z + d6, z1.w + d7);
    float sq = d0 * d0 + d1 * d1 + d2 * d2 + d3 * d3
             + d4 * d4 + d5 * d5 + d6 * d6 + d7 * d7;
#pragma unroll
    for (int off = 16; off > 0; off >>= 1) sq += __shfl_xor_sync(0xffffffffu, sq, off);
    if (lane == 0) {
        g_partials[row] = sq;
        atomicAdd(&g_counts[kbest], 1);
        if (write_idx) out[(size_t)n_rows * DD + 1 + row] = (float)kbest;
    }
}

// ============================================================================
// loss: deterministic reductions; vq_loss = (1+beta)*MSE - 0.01*perplexity
// ============================================================================
__global__ void vq_loss_kernel(float* __restrict__ out, int n_rows, int write_loss) {
    int tid = threadIdx.x;
    float s = 0.0f;
    for (int i = tid; i < n_rows; i += 1024) s += g_partials[i];
    float h = 0.0f;
    for (int k = tid; k < KC; k += 1024) {
        float p = (float)g_counts[k] / (float)n_rows;
        h -= p * logf(p + 1e-10f);
    }
    __shared__ float rs[1024];
    __shared__ float rh[1024];
    rs[tid] = s; rh[tid] = h;
    __syncthreads();
    for (int st = 512; st > 0; st >>= 1) {
        if (tid < st) { rs[tid] += rs[tid + st]; rh[tid] += rh[tid + st]; }
        __syncthreads();
    }
    if (tid == 0 && write_loss) {
        float mse = rs[0] / ((float)n_rows * (float)DD);
        float perplexity = expf(rh[0]);
        out[(size_t)n_rows * DD] = (1.0f + BETA_F) * mse - 0.01f * perplexity;
    }
}

// ============================================================================
extern "C" void kernel_launch(void* const* d_in, const int* in_sizes, int n_in,
                              void* d_out, int out_size) {
    (void)n_in;
    const float* Z = (const float*)d_in[0];   // z_e  [8,4096,256] fp32
    const float* W = (const float*)d_in[1];   // embed [2048,256] fp32
    float* out = (float*)d_out;

    int D = in_sizes[1] / KC;                  // 256
    int n_rows = in_sizes[0] / D;              // 32768
    long long nzq = (long long)n_rows * D;
    int write_loss = (out_size >= nzq + 1) ? 1 : 0;
    int write_idx  = (out_size >= nzq + 1 + n_rows) ? 1 : 0;

    cudaFuncSetAttribute(vq_imma_kernel,
                         cudaFuncAttributeMaxDynamicSharedMemorySize, SMEM_TOTAL);

    vq_prep_kernel<<<KC, 256>>>(W);
    vq_imma_kernel<<<n_rows / TILE_M, 256, SMEM_TOTAL>>>(Z);
    vq_refine_gather_kernel<<<n_rows / 8, 256>>>(Z, W, out, n_rows, write_idx);
    vq_loss_kernel<<<1, 1024>>>(out, n_rows, write_loss);
}

// round 9
// speedup vs baseline: 1.7559x; 1.7559x over previous
#include <cuda_runtime.h>
#include <cuda_bf16.h>
#include <cstdint>

// VQ-VAE eval forward, GB300 (sm_103a die, sm_103 base-ISA target).
// Round 8: HYBRID. Round 7 showed IMMA >> slower than HMMA per instr; round 6
// showed HMMA uses 1/60 of issue slots -> fma pipe idle. Split rows per CTA:
//   warps 0-7  : bf16 HMMA shortlist (rows 0-63)  + top-8 band -> exact refine
//   warps 8-11 : exact fp32 f32x2 argmin (rows 64-127), round-3-proven pipeline
// Both pipes run concurrently; groups use named barriers and disjoint smem.

#define KC      2048
#define DD      256
#define BETA_F  0.25f
#define MAXROWS 32768
#define MARGIN  0.05f

#define TILE_N  128
#define NTILES  (KC / TILE_N)   // 16
#define CTA_ROWS 128
#define ROWS_T  64              // tensor rows
#define NTHREADS 384

// ---- smem layout (bytes) ----
#define APITCH  264             // b16 units per tensor-A row (256 + 8 pad)
#define BPITCH  136             // b16 units per tensor-B row (128 + 8 pad)
#define OFF_AT  0
#define ATBYTES (ROWS_T * APITCH * 2)          // 33792
#define OFF_BT  ATBYTES
#define BTBYTES (TILE_N * BPITCH * 2)          // 34816
#define OFF_US  (OFF_BT + 2 * BTBYTES)         // 103424
#define USBYTES (ROWS_T * 128 * 4)             // 32768
#define OFF_E2S (OFF_US + USBYTES)             // 136192
#define AFP     68                              // floats per fma-A k-row (64+4)
#define OFF_AF  (OFF_E2S + 512)                // 136704
#define AFBYTES (256 * AFP * 4)                // 69632
#define BFP     132                             // floats per fma-B k-row (128+4)
#define OFF_BF  (OFF_AF + AFBYTES)             // 206336
#define BFBYTES (16 * BFP * 4)                 // 8448
#define SMEM_TOTAL (OFF_BF + 2 * BFBYTES)      // 223232

// ---- static device scratch ----
__device__ float          g_e2[KC];
__device__ float          g_z2[MAXROWS];
__device__ __nv_bfloat16  g_Wbf[KC * DD];
__device__ int            g_cand[MAXROWS * 8];
__device__ int            g_ncand[MAXROWS];
__device__ int            g_counts[KC];
__device__ float          g_partials[MAXROWS];

// ============================================================================
// helpers
// ============================================================================
__device__ __forceinline__ uint32_t smem_u32(const void* p) {
    uint32_t a;
    asm("{ .reg .u64 t; cvta.to.shared.u64 t, %1; cvt.u32.u64 %0, t; }" : "=r"(a) : "l"(p));
    return a;
}
__device__ __forceinline__ void ldsm_x4(uint32_t& r0, uint32_t& r1, uint32_t& r2,
                                        uint32_t& r3, uint32_t addr) {
    asm volatile("ldmatrix.sync.aligned.m8n8.x4.shared.b16 {%0,%1,%2,%3}, [%4];"
                 : "=r"(r0), "=r"(r1), "=r"(r2), "=r"(r3) : "r"(addr));
}
__device__ __forceinline__ void mma16816(float* c, const uint32_t* a, const uint32_t* b) {
    asm volatile("mma.sync.aligned.m16n8k16.row.col.f32.bf16.bf16.f32 "
                 "{%0,%1,%2,%3}, {%4,%5,%6,%7}, {%8,%9}, {%0,%1,%2,%3};"
                 : "+f"(c[0]), "+f"(c[1]), "+f"(c[2]), "+f"(c[3])
                 : "r"(a[0]), "r"(a[1]), "r"(a[2]), "r"(a[3]), "r"(b[0]), "r"(b[1]));
}
__device__ __forceinline__ unsigned long long pk2(float x, float y) {
    unsigned long long r;
    asm("mov.b64 %0, {%1, %2};" : "=l"(r) : "f"(x), "f"(y));
    return r;
}
__device__ __forceinline__ void fma2(unsigned long long& c, unsigned long long a,
                                     unsigned long long b) {
    asm("fma.rn.f32x2 %0, %1, %2, %0;" : "+l"(c) : "l"(a), "l"(b));
}
__device__ __forceinline__ float2 upk2(unsigned long long v) {
    float2 r;
    asm("mov.b64 {%0, %1}, %2;" : "=f"(r.x), "=f"(r.y) : "l"(v));
    return r;
}
__device__ __forceinline__ int fswz(int r) {
    return (r & 1) | (((r >> 3) & 3) << 1) | (((r >> 1) & 3) << 3);
}
#define BAR_T() asm volatile("bar.sync 1, 256;" ::: "memory")
#define BAR_F() asm volatile("bar.sync 2, 128;" ::: "memory")

// ============================================================================
// prep kernels (launch order puts the hybrid kernel at profiled index 3)
// ============================================================================
__global__ void vq_prep_e2_kernel(const float* __restrict__ W) {
    int row = blockIdx.x, tid = threadIdx.x;
    float w = W[(size_t)row * DD + tid];
    __shared__ float red[256];
    red[tid] = w * w;
    __syncthreads();
    for (int s = 128; s > 0; s >>= 1) {
        if (tid < s) red[tid] += red[tid + s];
        __syncthreads();
    }
    if (tid == 0) { g_e2[row] = red[0]; g_counts[row] = 0; }
}

__global__ void vq_prep_z2_kernel(const float* __restrict__ Z) {
    int row = blockIdx.x, tid = threadIdx.x;
    float z = Z[(size_t)row * DD + tid];
    __shared__ float red[256];
    red[tid] = z * z;
    __syncthreads();
    for (int s = 128; s > 0; s >>= 1) {
        if (tid < s) red[tid] += red[tid + s];
        __syncthreads();
    }
    if (tid == 0) g_z2[row] = red[0];
}

__global__ void vq_prep_wbf_kernel(const float* __restrict__ W) {
    int i = blockIdx.x * 256 + threadIdx.x;
    g_Wbf[i] = __float2bfloat16_rn(W[i]);
}

// ============================================================================
// hybrid phase-1 kernel: 384 threads, grid = n_rows/128, 1 CTA/SM.
// ============================================================================
__global__ __launch_bounds__(NTHREADS, 1)
void vq_hybrid_kernel(const float* __restrict__ Z, const float* __restrict__ W) {
    extern __shared__ char smem[];
    const uint32_t sb = smem_u32(smem);
    const int tid = threadIdx.x;
    const int lane = tid & 31, wid = tid >> 5;
    const int rowBase = blockIdx.x * CTA_ROWS;

    if (wid < 8) {
        // ==================== TENSOR GROUP: rows rowBase..+63 ====================
        const int wm = wid & 1, wn = wid >> 1;      // wm: 32-row half, wn: 32-col quarter
        const int grp = lane >> 3, lr = lane & 7;
        float* Us  = (float*)(smem + OFF_US);
        float* e2s = (float*)(smem + OFF_E2S);

        uint32_t aAddr[2];
#pragma unroll
        for (int f = 0; f < 2; ++f) {
            int r = wm * 32 + f * 16 + (grp & 1) * 8 + lr;
            int kof = (grp >> 1) * 8;
            aAddr[f] = sb + OFF_AT + (uint32_t)(r * APITCH + kof) * 2u;
        }
        uint32_t bAddr[2];
#pragma unroll
        for (int p = 0; p < 2; ++p) {
            int n = wn * 32 + p * 16 + (grp >> 1) * 8 + lr;
            int kof = (grp & 1) * 8;
            bAddr[p] = sb + OFF_BT + (uint32_t)(n * BPITCH + kof) * 2u;
        }

        // A: 64 rows x 256 fp32 -> bf16 smem (256 threads: 4 per row)
        {
            int r = tid >> 2, q = tid & 3;
            const float4* src = (const float4*)(Z + (size_t)(rowBase + r) * DD + q * 64);
            __nv_bfloat162* dst = (__nv_bfloat162*)(smem + OFF_AT) + r * (APITCH / 2) + q * 32;
#pragma unroll 8
            for (int j = 0; j < 16; ++j) {
                float4 v = src[j];
                dst[j * 2]     = __float22bfloat162_rn(make_float2(v.x, v.y));
                dst[j * 2 + 1] = __float22bfloat162_rn(make_float2(v.z, v.w));
            }
        }

        float u0 = 3.4e38f, u1 = 3.4e38f, u2 = 3.4e38f, u3 = 3.4e38f,
              u4 = 3.4e38f, u5 = 3.4e38f, u6 = 3.4e38f, u7 = 3.4e38f;
        int   k0 = 0, k1 = 0, k2 = 0, k3 = 0, k4 = 0, k5 = 0, k6 = 0, k7 = 0;
        const int myf = fswz(tid & 63);

        float acc[2][4][4];
        uint4 rb[8];
        {   // prefetch B tile 0
            int n = tid >> 1, hf = tid & 1;
            const uint4* src = (const uint4*)g_Wbf + ((size_t)n * DD + hf * 64) / 8;
#pragma unroll
            for (int j = 0; j < 8; ++j) rb[j] = src[j];
        }

        for (int t = 0; t < 2 * NTILES; ++t) {
            const int nt = t >> 1, kt = t & 1, buf = t & 1;
            const uint32_t bufOff = (uint32_t)buf * BTBYTES;

            BAR_T();
            {   // store prefetched regs -> Bt[buf]
                int n = tid >> 1, hf = tid & 1;
                uint4* dst = (uint4*)(smem + OFF_BT + bufOff) + (n * (BPITCH / 8) + hf * 8);
#pragma unroll
                for (int j = 0; j < 8; ++j) dst[j] = rb[j];
            }
            if (kt == 0 && tid < 128) e2s[tid] = g_e2[nt * 128 + tid];
            if (t + 1 < 2 * NTILES) {
                int tn = t + 1;
                int n = tid >> 1, hf = tid & 1;
                const uint4* src = (const uint4*)g_Wbf +
                    ((size_t)((tn >> 1) * 128 + n) * DD + (tn & 1) * 128 + hf * 64) / 8;
#pragma unroll
                for (int j = 0; j < 8; ++j) rb[j] = src[j];
            }
            BAR_T();

            if (kt == 0) {
#pragma unroll
                for (int mf = 0; mf < 2; ++mf)
#pragma unroll
                    for (int nf = 0; nf < 4; ++nf)
#pragma unroll
                        for (int c = 0; c < 4; ++c) acc[mf][nf][c] = 0.0f;
            }

#pragma unroll
            for (int ks = 0; ks < 8; ++ks) {
                uint32_t a[2][4], b[4][2];
                ldsm_x4(a[0][0], a[0][1], a[0][2], a[0][3],
                        aAddr[0] + (uint32_t)(kt * 128 + ks * 16) * 2u);
                ldsm_x4(a[1][0], a[1][1], a[1][2], a[1][3],
                        aAddr[1] + (uint32_t)(kt * 128 + ks * 16) * 2u);
#pragma unroll
                for (int p = 0; p < 2; ++p)
                    ldsm_x4(b[2 * p][0], b[2 * p][1], b[2 * p + 1][0], b[2 * p + 1][1],
                            bAddr[p] + bufOff + (uint32_t)(ks * 16) * 2u);
#pragma unroll
                for (int mf = 0; mf < 2; ++mf)
#pragma unroll
                    for (int nf = 0; nf < 4; ++nf)
                        mma16816(acc[mf][nf], a[mf], b[nf]);
            }

            if (kt == 1) {
#pragma unroll
                for (int mf = 0; mf < 2; ++mf) {
                    int r0 = wm * 32 + mf * 16 + (lane >> 2);
                    int r1 = r0 + 8;
#pragma unroll
                    for (int nf = 0; nf < 4; ++nf) {
                        int c0 = wn * 32 + nf * 8 + 2 * (lane & 3);
                        float e0 = e2s[c0], e1 = e2s[c0 + 1];
                        Us[r0 * 128 + ((c0)     ^ fswz(r0))] = fmaf(-2.0f, acc[mf][nf][0], e0);
                        Us[r0 * 128 + ((c0 + 1) ^ fswz(r0))] = fmaf(-2.0f, acc[mf][nf][1], e1);
                        Us[r1 * 128 + ((c0)     ^ fswz(r1))] = fmaf(-2.0f, acc[mf][nf][2], e0);
                        Us[r1 * 128 + ((c0 + 1) ^ fswz(r1))] = fmaf(-2.0f, acc[mf][nf][3], e1);
                    }
                }
                BAR_T();
                if (tid < 64) {
                    const float* urow = Us + tid * 128;
                    int kbase = nt * 128;
#pragma unroll 4
                    for (int c = 0; c < 128; ++c) {
                        float u = urow[c ^ myf];
                        if (u < u7) {
                            u7 = u; k7 = kbase + c;
                            if (u7 < u6) { float tu = u6; u6 = u7; u7 = tu; int tk = k6; k6 = k7; k7 = tk; }
                            if (u6 < u5) { float tu = u5; u5 = u6; u6 = tu; int tk = k5; k5 = k6; k6 = tk; }
                            if (u5 < u4) { float tu = u4; u4 = u5; u5 = tu; int tk = k4; k4 = k5; k5 = tk; }
                            if (u4 < u3) { float tu = u3; u3 = u4; u4 = tu; int tk = k3; k3 = k4; k4 = tk; }
                            if (u3 < u2) { float tu = u2; u2 = u3; u3 = tu; int tk = k2; k2 = k3; k3 = tk; }
                            if (u2 < u1) { float tu = u1; u1 = u2; u2 = tu; int tk = k1; k1 = k2; k2 = tk; }
                            if (u1 < u0) { float tu = u0; u0 = u1; u1 = tu; int tk = k0; k0 = k1; k1 = tk; }
                        }
                    }
                }
            }
        }

        if (tid < 64) {
            int row = rowBase + tid;
            float thr = u0 + MARGIN;
            int cnt = 1 + (u1 <= thr) + (u2 <= thr) + (u3 <= thr) + (u4 <= thr)
                        + (u5 <= thr) + (u6 <= thr) + (u7 <= thr);
            g_cand[row * 8 + 0] = k0; g_cand[row * 8 + 1] = k1;
            g_cand[row * 8 + 2] = k2; g_cand[row * 8 + 3] = k3;
            g_cand[row * 8 + 4] = k4; g_cand[row * 8 + 5] = k5;
            g_cand[row * 8 + 6] = k6; g_cand[row * 8 + 7] = k7;
            g_ncand[row] = (cnt == 8) ? 9 : cnt;
        }
    } else {
        // ==================== FMA GROUP: rows rowBase+64..+127 ====================
        const int tidf = tid - 256;               // 0..127
        const int tm = tidf >> 4, tn = tidf & 15; // 8 rows x 8 cols microtile
        float* Af = (float*)(smem + OFF_AF);      // [k][row], stride AFP
        float* Bf = (float*)(smem + OFF_BF);      // 2 x [16][BFP]

        // A fill: rows 64-127 fp32, transposed to [k][row]
        {
            int r = tidf >> 1, hf = tidf & 1;
            const float4* src = (const float4*)(Z + (size_t)(rowBase + 64 + r) * DD + hf * 128);
#pragma unroll 8
            for (int j = 0; j < 32; ++j) {
                float4 v = src[j];
                int kk = hf * 128 + j * 4;
                Af[(kk + 0) * AFP + r] = v.x;
                Af[(kk + 1) * AFP + r] = v.y;
                Af[(kk + 2) * AFP + r] = v.z;
                Af[(kk + 3) * AFP + r] = v.w;
            }
        }

        float z2r[8];
#pragma unroll
        for (int i = 0; i < 8; ++i) z2r[i] = g_z2[rowBase + 64 + tm * 8 + i];

        float best[8];
        int   bidx[8];
#pragma unroll
        for (int i = 0; i < 8; ++i) { best[i] = 3.4e38f; bidx[i] = 0; }

        // prefetch chunk 0 (nt=0, kt=0)
        float4 pf[4];
        {
            int col = (tidf * 4) >> 2;            // = tidf
#pragma unroll
            for (int j = 0; j < 4; ++j)
                pf[j] = *(const float4*)&W[(size_t)col * DD + j * 4];
        }
        BAR_F();   // Af visible (also covers first Bf store ordering below)

        for (int nt = 0; nt < NTILES; ++nt) {
            const int colBase = nt * TILE_N;
            unsigned long long acc2[8][4];
#pragma unroll
            for (int i = 0; i < 8; ++i)
#pragma unroll
                for (int jp = 0; jp < 4; ++jp) acc2[i][jp] = 0ull;

            for (int kt = 0; kt < 16; ++kt) {
                const int buf = kt & 1;
                {   // store prefetched chunk -> Bf[buf]  (thread covers col=tidf, q=j)
                    float* dst = Bf + buf * 16 * BFP;
#pragma unroll
                    for (int j = 0; j < 4; ++j) {
                        dst[(j * 4 + 0) * BFP + tidf] = pf[j].x;
                        dst[(j * 4 + 1) * BFP + tidf] = pf[j].y;
                        dst[(j * 4 + 2) * BFP + tidf] = pf[j].z;
                        dst[(j * 4 + 3) * BFP + tidf] = pf[j].w;
                    }
                }
                {   // prefetch next chunk
                    int g = nt * 16 + kt + 1;
                    if (g < NTILES * 16) {
                        int nnt = g >> 4, nkt = g & 15;
#pragma unroll
                        for (int j = 0; j < 4; ++j)
                            pf[j] = *(const float4*)&W[(size_t)(nnt * 128 + tidf) * DD
                                                       + nkt * 16 + j * 4];
                    }
                }
                BAR_F();
#pragma unroll
                for (int kk = 0; kk < 16; ++kk) {
                    float a[8];
                    const float* arow = Af + (kt * 16 + kk) * AFP + tm * 8;
                    *(float4*)&a[0] = *(const float4*)&arow[0];
                    *(float4*)&a[4] = *(const float4*)&arow[4];
                    const unsigned long long* bp =
                        (const unsigned long long*)(Bf + buf * 16 * BFP + kk * BFP + tn * 8);
                    unsigned long long b2[4];
                    b2[0] = bp[0]; b2[1] = bp[1]; b2[2] = bp[2]; b2[3] = bp[3];
#pragma unroll
                    for (int i = 0; i < 8; ++i) {
                        unsigned long long a2 = pk2(a[i], a[i]);
                        fma2(acc2[i][0], a2, b2[0]);
                        fma2(acc2[i][1], a2, b2[1]);
                        fma2(acc2[i][2], a2, b2[2]);
                        fma2(acc2[i][3], a2, b2[3]);
                    }
                }
            }

            // epilogue: exact reference ranking (round-3-proven)
            float e2v[8];
            *(float4*)&e2v[0] = *(const float4*)&g_e2[colBase + tn * 8];
            *(float4*)&e2v[4] = *(const float4*)&g_e2[colBase + tn * 8 + 4];
#pragma unroll
            for (int i = 0; i < 8; ++i) {
#pragma unroll
                for (int jp = 0; jp < 4; ++jp) {
                    float2 d = upk2(acc2[i][jp]);
                    int kcode = colBase + tn * 8 + jp * 2;
                    float uu0 = (z2r[i] - 2.0f * d.x) + e2v[jp * 2];
                    float uu1 = (z2r[i] - 2.0f * d.y) + e2v[jp * 2 + 1];
                    float s0 = sqrtf(fmaxf(uu0, 0.0f));
                    float s1 = sqrtf(fmaxf(uu1, 0.0f));
                    if (s0 < best[i]) { best[i] = s0; bidx[i] = kcode; }
                    if (s1 < best[i]) { best[i] = s1; bidx[i] = kcode + 1; }
                }
            }
        }

        // merge across 16 tn lanes (contiguous in-warp); ties -> lowest index
#pragma unroll
        for (int i = 0; i < 8; ++i) {
            float s = best[i];
            int b = bidx[i];
#pragma unroll
            for (int off = 8; off > 0; off >>= 1) {
                float so = __shfl_xor_sync(0xffffffffu, s, off);
                int   bo = __shfl_xor_sync(0xffffffffu, b, off);
                if (so < s || (so == s && bo < b)) { s = so; b = bo; }
            }
            if (tn == 0) {
                int row = rowBase + 64 + tm * 8 + i;
                g_cand[row * 8] = b;
                g_ncand[row] = 1;
            }
        }
    }
}

// ============================================================================
// refine + gather (exact fp32 ranking over candidates; nc==1 -> pure gather)
// ============================================================================
__global__ __launch_bounds__(256)
void vq_refine_gather_kernel(const float* __restrict__ Z, const float* __restrict__ W,
                             float* __restrict__ out, int n_rows, int write_idx) {
    const int lane = threadIdx.x & 31;
    const int row = blockIdx.x * 8 + (threadIdx.x >> 5);

    float4 z0 = *(const float4*)&Z[(size_t)row * DD + lane * 8];
    float4 z1 = *(const float4*)&Z[(size_t)row * DD + lane * 8 + 4];
    float p = z0.x * z0.x + z0.y * z0.y + z0.z * z0.z + z0.w * z0.w
            + z1.x * z1.x + z1.y * z1.y + z1.z * z1.z + z1.w * z1.w;
#pragma unroll
    for (int off = 16; off > 0; off >>= 1) p += __shfl_xor_sync(0xffffffffu, p, off);
    const float z2 = p;

    int nc = g_ncand[row];
    float sbest = 3.4e38f;
    int kbest = 0;
    if (nc == 1) {
        kbest = g_cand[row * 8];
    } else {
        int iters = (nc <= 8) ? nc : KC;
        for (int i = 0; i < iters; ++i) {
            int k = (nc <= 8) ? g_cand[row * 8 + i] : i;
            float4 w0 = *(const float4*)&W[(size_t)k * DD + lane * 8];
            float4 w1 = *(const float4*)&W[(size_t)k * DD + lane * 8 + 4];
            float d = z0.x * w0.x + z0.y * w0.y + z0.z * w0.z + z0.w * w0.w
                    + z1.x * w1.x + z1.y * w1.y + z1.z * w1.z + z1.w * w1.w;
#pragma unroll
            for (int off = 16; off > 0; off >>= 1) d += __shfl_xor_sync(0xffffffffu, d, off);
            float u = (z2 - 2.0f * d) + g_e2[k];
            float s = sqrtf(fmaxf(u, 0.0f));
            if (s < sbest || (s == sbest && k < kbest)) { sbest = s; kbest = k; }
        }
    }

    float4 w0 = *(const float4*)&W[(size_t)kbest * DD + lane * 8];
    float4 w1 = *(const float4*)&W[(size_t)kbest * DD + lane * 8 + 4];
    float d0 = w0.x - z0.x, d1 = w0.y - z0.y, d2 = w0.z - z0.z, d3 = w0.w - z0.w;
    float d4 = w1.x - z1.x, d5 = w1.y - z1.y, d6 = w1.z - z1.z, d7 = w1.w - z1.w;
    *(float4*)&out[(size_t)row * DD + lane * 8] =
        make_float4(z0.x + d0, z0.y + d1, z0.z + d2, z0.w + d3);
    *(float4*)&out[(size_t)row * DD + lane * 8 + 4] =
        make_float4(z1.x + d4, z1.y + d5, z1.z + d6, z1.w + d7);
    float sq = d0 * d0 + d1 * d1 + d2 * d2 + d3 * d3
             + d4 * d4 + d5 * d5 + d6 * d6 + d7 * d7;
#pragma unroll
    for (int off = 16; off > 0; off >>= 1) sq += __shfl_xor_sync(0xffffffffu, sq, off);
    if (lane == 0) {
        g_partials[row] = sq;
        atomicAdd(&g_counts[kbest], 1);
        if (write_idx) out[(size_t)n_rows * DD + 1 + row] = (float)kbest;
    }
}

// ============================================================================
// loss
// ============================================================================
__global__ void vq_loss_kernel(float* __restrict__ out, int n_rows, int write_loss) {
    int tid = threadIdx.x;
    float s = 0.0f;
    for (int i = tid; i < n_rows; i += 1024) s += g_partials[i];
    float h = 0.0f;
    for (int k = tid; k < KC; k += 1024) {
        float p = (float)g_counts[k] / (float)n_rows;
        h -= p * logf(p + 1e-10f);
    }
    __shared__ float rs[1024];
    __shared__ float rh[1024];
    rs[tid] = s; rh[tid] = h;
    __syncthreads();
    for (int st = 512; st > 0; st >>= 1) {
        if (tid < st) { rs[tid] += rs[tid + st]; rh[tid] += rh[tid + st]; }
        __syncthreads();
    }
    if (tid == 0 && write_loss) {
        float mse = rs[0] / ((float)n_rows * (float)DD);
        float perplexity = expf(rh[0]);
        out[(size_t)n_rows * DD] = (1.0f + BETA_F) * mse - 0.01f * perplexity;
    }
}

// ============================================================================
extern "C" void kernel_launch(void* const* d_in, const int* in_sizes, int n_in,
                              void* d_out, int out_size) {
    (void)n_in;
    const float* Z = (const float*)d_in[0];
    const float* W = (const float*)d_in[1];
    float* out = (float*)d_out;

    int D = in_sizes[1] / KC;
    int n_rows = in_sizes[0] / D;
    long long nzq = (long long)n_rows * D;
    int write_loss = (out_size >= nzq + 1) ? 1 : 0;
    int write_idx  = (out_size >= nzq + 1 + n_rows) ? 1 : 0;

    cudaFuncSetAttribute(vq_hybrid_kernel,
                         cudaFuncAttributeMaxDynamicSharedMemorySize, SMEM_TOTAL);

    vq_prep_e2_kernel<<<KC, 256>>>(W);          // launch idx 0
    vq_prep_z2_kernel<<<n_rows, 256>>>(Z);      // idx 1
    vq_prep_wbf_kernel<<<(KC * DD) / 256, 256>>>(W);  // idx 2
    vq_hybrid_kernel<<<n_rows / CTA_ROWS, NTHREADS, SMEM_TOTAL>>>(Z, W);  // idx 3 (profiled)
    vq_refine_gather_kernel<<<n_rows / 8, 256>>>(Z, W, out, n_rows, write_idx);
    vq_loss_kernel<<<1, 1024>>>(out, n_rows, write_loss);
}

// round 12
// speedup vs baseline: 3.2698x; 1.8622x over previous
#include <cuda_runtime.h>
#include <cuda_bf16.h>
#include <cstdint>

// VQ-VAE eval forward, GB300 (sm_103a die, sm_103 base-ISA target).
// Round 9: round-6 HMMA shortlist kernel with 16 warps (4/SMSP) instead of 8.
// Round-8 profile showed tensor pipe 3.8% active while HMMA ran -> round 6 was
// LATENCY-bound (LDSM->HMMA chains, 2 warps/SMSP), not rate-bound. Double the
// warps, halve per-warp work: 4x4 warp grid over the same 128x128 tile.
// Numerics identical to round 6 (passed, rel_err 4.23e-7): bf16 HMMA approx
// scores -> per-row top-8 band (MARGIN) -> exact fp32 reference re-rank.

#define KC      2048
#define DD      256
#define BETA_F  0.25f
#define MAXROWS 32768
#define MARGIN  0.05f

#define TILE_M  128
#define TILE_N  128
#define NTILES  (KC / TILE_N)     // 16
#define NTHREADS 512

// smem layout (bytes)
#define APITCH  264               // bf16 units per A row (256 + 8 pad)
#define BPITCH  136               // bf16 units per B row (128 + 8 pad)
#define OFF_A   0
#define ABYTES  (TILE_M * APITCH * 2)              // 67584
#define OFF_B   ABYTES
#define BBYTES  (TILE_N * BPITCH * 2)              // 34816
#define OFF_US  (OFF_B + 2 * BBYTES)               // 137216
#define USBYTES (128 * 128 * 4)                    // 65536
#define OFF_E2  (OFF_US + USBYTES)                 // 202752
#define SMEM_TOTAL (OFF_E2 + 512)                  // 203264

// ---- static device scratch ----
__device__ float          g_e2[KC];
__device__ __nv_bfloat16  g_Wbf[KC * DD];
__device__ int            g_cand[MAXROWS * 8];
__device__ int            g_ncand[MAXROWS];
__device__ int            g_counts[KC];
__device__ float          g_partials[MAXROWS];

// ============================================================================
// helpers
// ============================================================================
__device__ __forceinline__ uint32_t smem_u32(const void* p) {
    uint32_t a;
    asm("{ .reg .u64 t; cvta.to.shared.u64 t, %1; cvt.u32.u64 %0, t; }" : "=r"(a) : "l"(p));
    return a;
}
__device__ __forceinline__ void ldsm_x4(uint32_t& r0, uint32_t& r1, uint32_t& r2,
                                        uint32_t& r3, uint32_t addr) {
    asm volatile("ldmatrix.sync.aligned.m8n8.x4.shared.b16 {%0,%1,%2,%3}, [%4];"
                 : "=r"(r0), "=r"(r1), "=r"(r2), "=r"(r3) : "r"(addr));
}
__device__ __forceinline__ void mma16816(float* c, const uint32_t* a, const uint32_t* b) {
    asm volatile("mma.sync.aligned.m16n8k16.row.col.f32.bf16.bf16.f32 "
                 "{%0,%1,%2,%3}, {%4,%5,%6,%7}, {%8,%9}, {%0,%1,%2,%3};"
                 : "+f"(c[0]), "+f"(c[1]), "+f"(c[2]), "+f"(c[3])
                 : "r"(a[0]), "r"(a[1]), "r"(a[2]), "r"(a[3]), "r"(b[0]), "r"(b[1]));
}
__device__ __forceinline__ int fswz(int r) {
    return (r & 1) | (((r >> 3) & 3) << 1) | (((r >> 1) & 3) << 3);
}

// ============================================================================
// prep kernels (launch order puts the HMMA kernel at profiled index 3)
// ============================================================================
__global__ void vq_prep_e2_kernel(const float* __restrict__ W) {
    int row = blockIdx.x, tid = threadIdx.x;
    float w = W[(size_t)row * DD + tid];
    __shared__ float red[256];
    red[tid] = w * w;
    __syncthreads();
    for (int s = 128; s > 0; s >>= 1) {
        if (tid < s) red[tid] += red[tid + s];
        __syncthreads();
    }
    if (tid == 0) { g_e2[row] = red[0]; g_counts[row] = 0; }
}

__global__ void vq_prep_wbf_kernel(const float* __restrict__ W) {
    int i = blockIdx.x * 256 + threadIdx.x;
    g_Wbf[i] = __float2bfloat16_rn(W[i]);
}

__global__ void vq_zero_ncand_kernel(int n_rows) {
    int i = blockIdx.x * 256 + threadIdx.x;
    if (i < n_rows) g_ncand[i] = 0;
}

// ============================================================================
// phase 1: HMMA approx-score GEMM + per-row top-8 candidate band.
// 512 threads (16 warps: 4x4 over 128x128 -> 32x32 per warp), grid = n_rows/128.
// ============================================================================
__global__ __launch_bounds__(NTHREADS, 1)
void vq_hmma_kernel(const float* __restrict__ Z) {
    extern __shared__ char smem[];
    const uint32_t sb = smem_u32(smem);
    const int tid = threadIdx.x;
    const int lane = tid & 31, wid = tid >> 5;
    const int wm = wid & 3, wn = wid >> 2;     // wm: 32-row group, wn: 32-col group
    const int grp = lane >> 3, lr = lane & 7;
    const int rowBase = blockIdx.x * TILE_M;
    float* Us = (float*)(smem + OFF_US);
    float* e2s = (float*)(smem + OFF_E2);

    // ---- ldmatrix lane addresses ----
    uint32_t aAddr[2];
#pragma unroll
    for (int f = 0; f < 2; ++f) {
        int r = wm * 32 + f * 16 + (grp & 1) * 8 + lr;
        int kof = (grp >> 1) * 8;
        aAddr[f] = sb + OFF_A + (uint32_t)(r * APITCH + kof) * 2u;
    }
    uint32_t bAddr[2];
#pragma unroll
    for (int p = 0; p < 2; ++p) {
        int n = wn * 32 + p * 16 + (grp >> 1) * 8 + lr;
        int kof = (grp & 1) * 8;
        bAddr[p] = sb + OFF_B + (uint32_t)(n * BPITCH + kof) * 2u;
    }

    // ---- load A tile: 128 rows x 256 dims fp32 -> bf16 smem (4 thr/row) ----
    {
        int r = tid >> 2, q = tid & 3;
        const float4* src = (const float4*)(Z + (size_t)(rowBase + r) * DD + q * 64);
        __nv_bfloat162* dst = (__nv_bfloat162*)(smem + OFF_A) + r * (APITCH / 2) + q * 32;
#pragma unroll 8
        for (int j = 0; j < 16; ++j) {
            float4 v = src[j];
            dst[j * 2]     = __float22bfloat162_rn(make_float2(v.x, v.y));
            dst[j * 2 + 1] = __float22bfloat162_rn(make_float2(v.z, v.w));
        }
    }

    // ---- top-8 state (ascending u; u0 = min) ----
    float u0 = 3.4e38f, u1 = 3.4e38f, u2 = 3.4e38f, u3 = 3.4e38f,
          u4 = 3.4e38f, u5 = 3.4e38f, u6 = 3.4e38f, u7 = 3.4e38f;
    int   k0 = 0, k1 = 0, k2 = 0, k3 = 0, k4 = 0, k5 = 0, k6 = 0, k7 = 0;
    const int myf = fswz(tid & 127);

    float acc[2][4][4];
    uint4 rb[4];

    // prefetch B tile 0 (32KB: 4 thr/code-row, 64B each)
    {
        int n = tid >> 2, q = tid & 3;
        const uint4* src = (const uint4*)g_Wbf + ((size_t)n * DD + q * 32) / 8;
#pragma unroll
        for (int j = 0; j < 4; ++j) rb[j] = src[j];
    }

    for (int t = 0; t < 2 * NTILES; ++t) {
        const int nt = t >> 1, kt = t & 1, buf = t & 1;
        const uint32_t bufOff = (uint32_t)buf * BBYTES;

        __syncthreads();                       // prior readers of Bs[buf] done
        {   // store prefetched regs -> Bs[buf]
            int n = tid >> 2, q = tid & 3;
            uint4* dst = (uint4*)(smem + OFF_B + bufOff) + (n * (BPITCH / 8) + q * 4);
#pragma unroll
            for (int j = 0; j < 4; ++j) dst[j] = rb[j];
        }
        if (kt == 0 && tid < 128) e2s[tid] = g_e2[nt * 128 + tid];
        if (t + 1 < 2 * NTILES) {              // prefetch next tile
            int tn = t + 1;
            int n = tid >> 2, q = tid & 3;
            const uint4* src = (const uint4*)g_Wbf +
                ((size_t)((tn >> 1) * 128 + n) * DD + (tn & 1) * 128 + q * 32) / 8;
#pragma unroll
            for (int j = 0; j < 4; ++j) rb[j] = src[j];
        }
        __syncthreads();                       // Bs[buf] visible

        if (kt == 0) {
#pragma unroll
            for (int mf = 0; mf < 2; ++mf)
#pragma unroll
                for (int nf = 0; nf < 4; ++nf)
#pragma unroll
                    for (int c = 0; c < 4; ++c) acc[mf][nf][c] = 0.0f;
        }

#pragma unroll
        for (int ks = 0; ks < 8; ++ks) {
            uint32_t a[2][4], b[4][2];
            ldsm_x4(a[0][0], a[0][1], a[0][2], a[0][3],
                    aAddr[0] + (uint32_t)(kt * 128 + ks * 16) * 2u);
            ldsm_x4(a[1][0], a[1][1], a[1][2], a[1][3],
                    aAddr[1] + (uint32_t)(kt * 128 + ks * 16) * 2u);
#pragma unroll
            for (int p = 0; p < 2; ++p)
                ldsm_x4(b[2 * p][0], b[2 * p][1], b[2 * p + 1][0], b[2 * p + 1][1],
                        bAddr[p] + bufOff + (uint32_t)(ks * 16) * 2u);
#pragma unroll
            for (int mf = 0; mf < 2; ++mf)
#pragma unroll
                for (int nf = 0; nf < 4; ++nf)
                    mma16816(acc[mf][nf], a[mf], b[nf]);
        }

        if (kt == 1) {
            // ---- stage u = e2 - 2*d into swizzled smem ----
#pragma unroll
            for (int mf = 0; mf < 2; ++mf) {
                int r0 = wm * 32 + mf * 16 + (lane >> 2);
                int r1 = r0 + 8;
#pragma unroll
                for (int nf = 0; nf < 4; ++nf) {
                    int c0 = wn * 32 + nf * 8 + 2 * (lane & 3);
                    float e0 = e2s[c0], e1 = e2s[c0 + 1];
                    Us[r0 * 128 + ((c0)     ^ fswz(r0))] = fmaf(-2.0f, acc[mf][nf][0], e0);
                    Us[r0 * 128 + ((c0 + 1) ^ fswz(r0))] = fmaf(-2.0f, acc[mf][nf][1], e1);
                    Us[r1 * 128 + ((c0)     ^ fswz(r1))] = fmaf(-2.0f, acc[mf][nf][2], e0);
                    Us[r1 * 128 + ((c0 + 1) ^ fswz(r1))] = fmaf(-2.0f, acc[mf][nf][3], e1);
                }
            }
            __syncthreads();
            if (tid < 128) {
                const float* urow = Us + tid * 128;
                int kbase = nt * 128;
#pragma unroll 4
                for (int c = 0; c < 128; ++c) {
                    float u = urow[c ^ myf];
                    if (u < u7) {
                        u7 = u; k7 = kbase + c;
                        if (u7 < u6) { float tu = u6; u6 = u7; u7 = tu; int tk = k6; k6 = k7; k7 = tk; }
                        if (u6 < u5) { float tu = u5; u5 = u6; u6 = tu; int tk = k5; k5 = k6; k6 = tk; }
                        if (u5 < u4) { float tu = u4; u4 = u5; u5 = tu; int tk = k4; k4 = k5; k5 = tk; }
                        if (u4 < u3) { float tu = u3; u3 = u4; u4 = tu; int tk = k3; k3 = k4; k4 = tk; }
                        if (u3 < u2) { float tu = u2; u2 = u3; u3 = tu; int tk = k2; k2 = k3; k3 = tk; }
                        if (u2 < u1) { float tu = u1; u1 = u2; u2 = tu; int tk = k1; k1 = k2; k2 = tk; }
                        if (u1 < u0) { float tu = u0; u0 = u1; u1 = tu; int tk = k0; k0 = k1; k1 = tk; }
                    }
                }
            }
            // scan finishes before the next loop-top __syncthreads
        }
    }

    if (tid < 128) {
        int row = rowBase + tid;
        float thr = u0 + MARGIN;
        int cnt = 1 + (u1 <= thr) + (u2 <= thr) + (u3 <= thr) + (u4 <= thr)
                    + (u5 <= thr) + (u6 <= thr) + (u7 <= thr);
        g_cand[row * 8 + 0] = k0; g_cand[row * 8 + 1] = k1;
        g_cand[row * 8 + 2] = k2; g_cand[row * 8 + 3] = k3;
        g_cand[row * 8 + 4] = k4; g_cand[row * 8 + 5] = k5;
        g_cand[row * 8 + 6] = k6; g_cand[row * 8 + 7] = k7;
        g_ncand[row] = (cnt == 8) ? 9 : cnt;   // 9 = overflow -> exact full scan
    }
}

// ============================================================================
// phase 2: exact fp32 re-rank of candidates (reference ranking pipeline,
// lexicographic (s,k) == first-index ties) fused with gather/MSE/histogram.
// warp per row; grid = n_rows/8, block 256.
// ============================================================================
__global__ __launch_bounds__(256)
void vq_refine_gather_kernel(const float* __restrict__ Z, const float* __restrict__ W,
                             float* __restrict__ out, int n_rows, int write_idx) {
    const int lane = threadIdx.x & 31;
    const int row = blockIdx.x * 8 + (threadIdx.x >> 5);

    float4 z0 = *(const float4*)&Z[(size_t)row * DD + lane * 8];
    float4 z1 = *(const float4*)&Z[(size_t)row * DD + lane * 8 + 4];
    float p = z0.x * z0.x + z0.y * z0.y + z0.z * z0.z + z0.w * z0.w
            + z1.x * z1.x + z1.y * z1.y + z1.z * z1.z + z1.w * z1.w;
#pragma unroll
    for (int off = 16; off > 0; off >>= 1) p += __shfl_xor_sync(0xffffffffu, p, off);
    const float z2 = p;

    int nc = g_ncand[row];
    float sbest = 3.4e38f;
    int kbest = 0;
    int iters = (nc <= 8) ? nc : KC;
    for (int i = 0; i < iters; ++i) {
        int k = (nc <= 8) ? g_cand[row * 8 + i] : i;
        float4 w0 = *(const float4*)&W[(size_t)k * DD + lane * 8];
        float4 w1 = *(const float4*)&W[(size_t)k * DD + lane * 8 + 4];
        float d = z0.x * w0.x + z0.y * w0.y + z0.z * w0.z + z0.w * w0.w
                + z1.x * w1.x + z1.y * w1.y + z1.z * w1.z + z1.w * w1.w;
#pragma unroll
        for (int off = 16; off > 0; off >>= 1) d += __shfl_xor_sync(0xffffffffu, d, off);
        float u = (z2 - 2.0f * d) + g_e2[k];
        float s = sqrtf(fmaxf(u, 0.0f));
        if (s < sbest || (s == sbest && k < kbest)) { sbest = s; kbest = k; }
    }

    // ---- gather + MSE partial + histogram ----
    float4 w0 = *(const float4*)&W[(size_t)kbest * DD + lane * 8];
    float4 w1 = *(const float4*)&W[(size_t)kbest * DD + lane * 8 + 4];
    float d0 = w0.x - z0.x, d1 = w0.y - z0.y, d2 = w0.z - z0.z, d3 = w0.w - z0.w;
    float d4 = w1.x - z1.x, d5 = w1.y - z1.y, d6 = w1.z - z1.z, d7 = w1.w - z1.w;
    *(float4*)&out[(size_t)row * DD + lane * 8] =
        make_float4(z0.x + d0, z0.y + d1, z0.z + d2, z0.w + d3);
    *(float4*)&out[(size_t)row * DD + lane * 8 + 4] =
        make_float4(z1.x + d4, z1.y + d5, z1.z + d6, z1.w + d7);
    float sq = d0 * d0 + d1 * d1 + d2 * d2 + d3 * d3
             + d4 * d4 + d5 * d5 + d6 * d6 + d7 * d7;
#pragma unroll
    for (int off = 16; off > 0; off >>= 1) sq += __shfl_xor_sync(0xffffffffu, sq, off);
    if (lane == 0) {
        g_partials[row] = sq;
        atomicAdd(&g_counts[kbest], 1);
        if (write_idx) out[(size_t)n_rows * DD + 1 + row] = (float)kbest;
    }
}

// ============================================================================
// loss: deterministic reductions; vq_loss = (1+beta)*MSE - 0.01*perplexity
// ============================================================================
__global__ void vq_loss_kernel(float* __restrict__ out, int n_rows, int write_loss) {
    int tid = threadIdx.x;
    float s = 0.0f;
    for (int i = tid; i < n_rows; i += 1024) s += g_partials[i];
    float h = 0.0f;
    for (int k = tid; k < KC; k += 1024) {
        float p = (float)g_counts[k] / (float)n_rows;
        h -= p * logf(p + 1e-10f);
    }
    __shared__ float rs[1024];
    __shared__ float rh[1024];
    rs[tid] = s; rh[tid] = h;
    __syncthreads();
    for (int st = 512; st > 0; st >>= 1) {
        if (tid < st) { rs[tid] += rs[tid + st]; rh[tid] += rh[tid + st]; }
        __syncthreads();
    }
    if (tid == 0 && write_loss) {
        float mse = rs[0] / ((float)n_rows * (float)DD);
        float perplexity = expf(rh[0]);
        out[(size_t)n_rows * DD] = (1.0f + BETA_F) * mse - 0.01f * perplexity;
    }
}

// ============================================================================
extern "C" void kernel_launch(void* const* d_in, const int* in_sizes, int n_in,
                              void* d_out, int out_size) {
    (void)n_in;
    const float* Z = (const float*)d_in[0];   // z_e  [8,4096,256] fp32
    const float* W = (const float*)d_in[1];   // embed [2048,256] fp32
    float* out = (float*)d_out;

    int D = in_sizes[1] / KC;                  // 256
    int n_rows = in_sizes[0] / D;              // 32768
    long long nzq = (long long)n_rows * D;
    int write_loss = (out_size >= nzq + 1) ? 1 : 0;
    int write_idx  = (out_size >= nzq + 1 + n_rows) ? 1 : 0;

    cudaFuncSetAttribute(vq_hmma_kernel,
                         cudaFuncAttributeMaxDynamicSharedMemorySize, SMEM_TOTAL);

    vq_prep_e2_kernel<<<KC, 256>>>(W);                         // idx 0
    vq_prep_wbf_kernel<<<(KC * DD) / 256, 256>>>(W);           // idx 1
    vq_zero_ncand_kernel<<<(n_rows + 255) / 256, 256>>>(n_rows); // idx 2
    vq_hmma_kernel<<<n_rows / TILE_M, NTHREADS, SMEM_TOTAL>>>(Z); // idx 3 (profiled)
    vq_refine_gather_kernel<<<n_rows / 8, 256>>>(Z, W, out, n_rows, write_idx);
    vq_loss_kernel<<<1, 1024>>>(out, n_rows, write_loss);
}